// round 6
// baseline (speedup 1.0000x reference)
#include <cuda_runtime.h>
#include <stdint.h>

#define BATCH 4
#define HEADS 32
#define SEQ   4096
#define DK    128
#define VEC_PER_ROW (DK / 4)      // 32 float4 per d_k row
#define BH (BATCH * HEADS)        // 128 batch-head slices
#define PLANE (SEQ * VEC_PER_ROW) // 131072 float4 per bh slice

// Single fused kernel. Thread t handles one (s, d4) slot across 4 bh slices.
// It gathers its own (c, -s) pairs directly from the block-diagonal R:
//   R[pos, 2p, 2p] = c_p,  R[pos, 2p, 2p+1] = -s_p   (adjacent -> float2 load)
// For d4 (two pairs p0=2*d4, p1=2*d4+1):
//   pair0 float2 at element offset pos*16384 + d4*516
//   pair1 float2 at element offset pos*16384 + d4*516 + 258
// All loads (tp, 2x R, 4x x) are independent per-thread work; no barrier.
__global__ void __launch_bounds__(256)
rope_one(const float4* __restrict__ x, float4* __restrict__ out,
         const float* __restrict__ R, const int* __restrict__ tp) {
    unsigned t   = blockIdx.x * blockDim.x + threadIdx.x;
    unsigned r   = t & (PLANE - 1);       // (s, d4) within a slice
    unsigned bh4 = t >> 17;               // group of 4 bh slices (0..31)
    unsigned s   = r >> 5;
    unsigned d4  = r & 31;

    // Position gather (tp is 16 KB, L2/L1 resident).
    int pos = __ldg(&tp[s]);

    const float* Rp = R + (size_t)pos * (DK * DK) + d4 * 516u;
    // Front-batch the two R gathers (L2 hits after first toucher)...
    float2 a = __ldg(reinterpret_cast<const float2*>(Rp));         // (c0, -s0)
    float2 b = __ldg(reinterpret_cast<const float2*>(Rp + 258));   // (c1, -s1)

    unsigned base = bh4 * (4u * PLANE) + r;

    // ...together with the 4 independent streamed x loads.
    float4 x0 = __ldcs(&x[base + 0u * PLANE]);
    float4 x1 = __ldcs(&x[base + 1u * PLANE]);
    float4 x2 = __ldcs(&x[base + 2u * PLANE]);
    float4 x3 = __ldcs(&x[base + 3u * PLANE]);

    // o.even = c*xe - s*xo = a.x*xe + a.y*xo
    // o.odd  = s*xe + c*xo = -a.y*xe + a.x*xo
    float4 o0, o1, o2, o3;
    #define ROT(o, xi)                                  \
        o.x = fmaf(a.x, xi.x,  a.y * xi.y);             \
        o.y = fmaf(a.x, xi.y, -a.y * xi.x);             \
        o.z = fmaf(b.x, xi.z,  b.y * xi.w);             \
        o.w = fmaf(b.x, xi.w, -b.y * xi.z);
    ROT(o0, x0) ROT(o1, x1) ROT(o2, x2) ROT(o3, x3)
    #undef ROT

    __stcs(&out[base + 0u * PLANE], o0);
    __stcs(&out[base + 1u * PLANE], o1);
    __stcs(&out[base + 2u * PLANE], o2);
    __stcs(&out[base + 3u * PLANE], o3);
}

extern "C" void kernel_launch(void* const* d_in, const int* in_sizes, int n_in,
                              void* d_out, int out_size) {
    const float* x  = (const float*)d_in[0];
    const int*   tp = (const int*)d_in[1];
    const float* R  = (const float*)d_in[2];
    float* out = (float*)d_out;

    // (BH/4) * PLANE = 4,194,304 threads -> 16384 blocks of 256
    rope_one<<<(BH / 4) * PLANE / 256, 256>>>(
        (const float4*)x, (float4*)out, R, tp);
}

// round 7
// speedup vs baseline: 1.0746x; 1.0746x over previous
#include <cuda_runtime.h>
#include <stdint.h>

#define BATCH 4
#define HEADS 32
#define SEQ   4096
#define DK    128
#define HALF  (DK / 2)            // 64 rotation pairs
#define VEC_PER_ROW (DK / 4)      // 32 float4 per d_k row
#define BH (BATCH * HEADS)        // 128 batch-head slices
#define PLANE (SEQ * VEC_PER_ROW) // 131072 float4 per bh slice

// 2 MB table: per (seq position, float4-group) -> (c0, -s0, c1, -s1)
__device__ float4 g_cs[SEQ * VEC_PER_ROW];

// Kernel A: gather (c, -s) from block-diagonal R via token_positions.
// R[pos, 2p, 2p] = c, R[pos, 2p, 2p+1] = -s  -> one aligned float2 load/pair.
// Trigger PDL completion IMMEDIATELY: the dependent rope grid may launch and
// run its table-independent prologue while this kernel is still gathering.
// Correctness is preserved by cudaGridDependencySynchronize() in rope.
__global__ void build_cs_table(const float* __restrict__ R,
                               const int* __restrict__ token_positions) {
    cudaTriggerProgrammaticLaunchCompletion();
    int tid = blockIdx.x * blockDim.x + threadIdx.x;   // over SEQ * HALF
    if (tid < SEQ * HALF) {
        int p = tid & (HALF - 1);
        int s = tid >> 6;
        long long pos = token_positions[s];
        const float2* cm = reinterpret_cast<const float2*>(
            R + pos * (long long)(DK * DK) + (2 * p) * DK + 2 * p);
        float2 v = __ldg(cm);                          // (c, -s)
        reinterpret_cast<float2*>(g_cs)[s * HALF + p] = v;  // store as-is
    }
}

// Kernel B: one (s,d4) slot across 4 bh slices. All x loads are issued before
// the grid-dependency sync so they overlap kernel A.
// Table holds (c, -s):  o.even = c*xe + (-s)*xo ;  o.odd = c*xo - (-s)*xe
__global__ void __launch_bounds__(256)
rope_kernel(const float4* __restrict__ x, float4* __restrict__ out) {
    unsigned t = blockIdx.x * blockDim.x + threadIdx.x;
    unsigned r   = t & (PLANE - 1);                      // (s, d4) within a slice
    unsigned bh4 = t >> 17;                              // group of 4 slices

    unsigned base = bh4 * (4u * PLANE) + r;

    // Front-batch 4 independent streamed loads (no dependence on g_cs).
    float4 x0 = __ldcs(&x[base + 0u * PLANE]);
    float4 x1 = __ldcs(&x[base + 1u * PLANE]);
    float4 x2 = __ldcs(&x[base + 2u * PLANE]);
    float4 x3 = __ldcs(&x[base + 3u * PLANE]);

    cudaGridDependencySynchronize();

    float4 cs = g_cs[r];                                 // (c0,-s0,c1,-s1), L2 hit

    float4 o0, o1, o2, o3;
    #define ROT(o, xi)                                  \
        o.x = fmaf(cs.x, xi.x,  cs.y * xi.y);           \
        o.y = fmaf(cs.x, xi.y, -cs.y * xi.x);           \
        o.z = fmaf(cs.z, xi.z,  cs.w * xi.w);           \
        o.w = fmaf(cs.z, xi.w, -cs.w * xi.z);
    ROT(o0, x0) ROT(o1, x1) ROT(o2, x2) ROT(o3, x3)
    #undef ROT

    __stcs(&out[base + 0u * PLANE], o0);
    __stcs(&out[base + 1u * PLANE], o1);
    __stcs(&out[base + 2u * PLANE], o2);
    __stcs(&out[base + 3u * PLANE], o3);
}

extern "C" void kernel_launch(void* const* d_in, const int* in_sizes, int n_in,
                              void* d_out, int out_size) {
    const float* x  = (const float*)d_in[0];
    const int*   tp = (const int*)d_in[1];
    const float* R  = (const float*)d_in[2];
    float* out = (float*)d_out;

    build_cs_table<<<(SEQ * HALF + 255) / 256, 256>>>(R, tp);

    cudaLaunchConfig_t cfg = {};
    cfg.gridDim  = dim3((BH / 4) * PLANE / 256, 1, 1);   // 16384 blocks
    cfg.blockDim = dim3(256, 1, 1);
    cfg.dynamicSmemBytes = 0;
    cfg.stream = 0;
    cudaLaunchAttribute attr[1];
    attr[0].id = cudaLaunchAttributeProgrammaticStreamSerialization;
    attr[0].val.programmaticStreamSerializationAllowed = 1;
    cfg.attrs = attr;
    cfg.numAttrs = 1;
    cudaLaunchKernelEx(&cfg, rope_kernel, (const float4*)x, (float4*)out);
}